// round 9
// baseline (speedup 1.0000x reference)
#include <cuda_runtime.h>
#include <cuda_bf16.h>
#include <cstdint>

// ===================== Problem constants =====================

#define BATCH 4096
#define NTOT  8192
#define DIM   128
#define NTILES 2080                       // 64*65/2 upper triangle incl diagonal
#define GRID_K2 296                       // 2 CTAs per SM

#define ROW_BYTES 144                     // 128 fp8 = 128B + 16B pad (conflict-free ldmatrix)
#define TILE_BYTES (128 * ROW_BYTES)      // 18432
#define SLOT_BYTES (2 * TILE_BYTES)       // A stripe + B stripe = 36864
#define SMEM_BYTES (3 * SLOT_BYTES)       // 110592/CTA, triple-buffered (2 CTAs = 221KB/SM)

#define EXP_DIAG 7.3890560989306495f      // e^2 self-similarity exp

// ===================== asm helpers (sm_100-safe, fp8 is sm_89+ standard) =====================

__device__ __forceinline__ uint32_t smem_u32(const void* smem_ptr) {
    uint32_t addr;
    asm("{ .reg .u64 tmp; cvta.to.shared.u64 tmp, %1; cvt.u32.u64 %0, tmp; }"
        : "=r"(addr) : "l"(smem_ptr));
    return addr;
}

#define LDSM_X4(r, addr) \
    asm volatile("ldmatrix.sync.aligned.m8n8.x4.shared.b16 {%0,%1,%2,%3}, [%4];" \
        : "=r"((r)[0]), "=r"((r)[1]), "=r"((r)[2]), "=r"((r)[3]) : "r"(addr))

// fp8 e4m3 MMA, m16n8k32: same fragment addressing as bf16 m16n8k16 (b16 -> 2 fp8)
#define MMA_FP8(d, a, b0, b1) \
    asm volatile("mma.sync.aligned.m16n8k32.row.col.f32.e4m3.e4m3.f32 " \
        "{%0,%1,%2,%3}, {%4,%5,%6,%7}, {%8,%9}, {%0,%1,%2,%3};" \
        : "+f"((d)[0]), "+f"((d)[1]), "+f"((d)[2]), "+f"((d)[3]) \
        : "r"((a)[0]), "r"((a)[1]), "r"((a)[2]), "r"((a)[3]), "r"(b0), "r"(b1))

#define CP_ASYNC_16(dst_smem, src_gmem) \
    asm volatile("cp.async.cg.shared.global [%0], [%1], 16;" \
        :: "r"(dst_smem), "l"(src_gmem) : "memory")

#define CP_ASYNC_COMMIT() asm volatile("cp.async.commit_group;" ::: "memory")
#define CP_ASYNC_WAIT_1() asm volatile("cp.async.wait_group 1;" ::: "memory")
#define CP_ASYNC_WAIT_0() asm volatile("cp.async.wait_group 0;" ::: "memory")

// ---- packed f32x2 ----

typedef unsigned long long u64;

__device__ __forceinline__ u64 pk2(float lo, float hi) {
    u64 r;
    asm("mov.b64 %0, {%1, %2};" : "=l"(r) : "f"(lo), "f"(hi));
    return r;
}
__device__ __forceinline__ void upk2(float& lo, float& hi, u64 v) {
    asm("mov.b64 {%0, %1}, %2;" : "=f"(lo), "=f"(hi) : "l"(v));
}
__device__ __forceinline__ u64 fma2(u64 a, u64 b, u64 c) {
    u64 d;
    asm("fma.rn.f32x2 %0, %1, %2, %3;" : "=l"(d) : "l"(a), "l"(b), "l"(c));
    return d;
}
__device__ __forceinline__ constexpr u64 dup2c(float f) {
    union { float f32; unsigned int u32; } u = { f };
    return ((u64)u.u32 << 32) | u.u32;
}

// float4 -> 4 packed e4m3 (v.x in byte 0)
__device__ __forceinline__ uint32_t f4_to_e4m3(float4 v) {
    uint16_t h01, h23;
    asm("cvt.rn.satfinite.e4m3x2.f32 %0, %1, %2;" : "=h"(h01) : "f"(v.y), "f"(v.x));
    asm("cvt.rn.satfinite.e4m3x2.f32 %0, %1, %2;" : "=h"(h23) : "f"(v.w), "f"(v.z));
    return (uint32_t)h01 | ((uint32_t)h23 << 16);
}

// ===================== Device scratch =====================

__device__ uint8_t g_zn[NTOT * DIM];     // normalized rows, e4m3
__device__ float g_pos[BATCH];           // pos_r = sim(r, r+B)/T, fp32 exact
__device__ float g_rowsum[NTOT];         // sum of exp per row (atomics)
__device__ float g_loss;                 // final accumulation (atomics)

// ===================== K1: normalize + positives =====================

__global__ void __launch_bounds__(256) k1_normalize(const float* __restrict__ zi,
                                                    const float* __restrict__ zj) {
    const int tid = threadIdx.x;
    const int lane = tid & 31;
    const int r = blockIdx.x * 8 + (tid >> 5);   // 512 blocks x 8 warps

    const float4 va = reinterpret_cast<const float4*>(zi + r * DIM)[lane];
    const float4 vb = reinterpret_cast<const float4*>(zj + r * DIM)[lane];
    float sa  = va.x*va.x + va.y*va.y + va.z*va.z + va.w*va.w;
    float sb  = vb.x*vb.x + vb.y*vb.y + vb.z*vb.z + vb.w*vb.w;
    float sab = va.x*vb.x + va.y*vb.y + va.z*vb.z + va.w*vb.w;
    #pragma unroll
    for (int o = 16; o; o >>= 1) {
        sa  += __shfl_xor_sync(0xffffffffu, sa,  o);
        sb  += __shfl_xor_sync(0xffffffffu, sb,  o);
        sab += __shfl_xor_sync(0xffffffffu, sab, o);
    }
    const float ri = rsqrtf(fmaxf(sa, 1e-16f));
    const float rj = rsqrtf(fmaxf(sb, 1e-16f));

    float4 na = make_float4(va.x * ri, va.y * ri, va.z * ri, va.w * ri);
    float4 nb = make_float4(vb.x * rj, vb.y * rj, vb.z * rj, vb.w * rj);
    reinterpret_cast<uint32_t*>(g_zn + r * DIM)[lane]           = f4_to_e4m3(na);
    reinterpret_cast<uint32_t*>(g_zn + (r + BATCH) * DIM)[lane] = f4_to_e4m3(nb);

    if (lane == 0) g_pos[r] = sab * ri * rj * 2.0f;   // /T = *2
    if (blockIdx.x < 32) g_rowsum[blockIdx.x * 256 + tid] = 0.0f;
    if (blockIdx.x == 0 && tid == 0) g_loss = 0.0f;
}

// ===================== K2: symmetric fp8 GEMM + exp + row/col sums =====================
//
// 296 persistent CTAs (2/SM) over 2080 upper-triangle 128x128 tiles. 256 threads,
// warp grid 4x2. Triple-buffered -> ONE barrier per tile. Cross-CTA overlap.

__device__ __forceinline__ void decode_tile(int t, int& I, int& J) {
    int i = (int)(64.5f - sqrtf(64.5f * 64.5f - 2.0f * (float)t));
    while (i * (129 - i) / 2 > t) i--;
    while ((i + 1) * (128 - i) / 2 <= t) i++;
    I = i;
    J = i + (t - i * (129 - i) / 2);
}

__global__ void __launch_bounds__(256, 2) k2_simsum() {
    extern __shared__ __align__(16) char dynsm[];

    const int tid = threadIdx.x;
    const int wid = tid >> 5;
    const int lane = tid & 31;
    const int wm = wid & 3;        // 4 row bands of 32
    const int wn = wid >> 2;       // 2 col halves of 64

    auto issue = [&](int slot, int I, int J) {
        char* bufA = dynsm + slot * SLOT_BYTES;
        #pragma unroll
        for (int i = 0; i < 4; i++) {
            const int idx = tid + i * 256, row = idx >> 3, c = idx & 7;
            CP_ASYNC_16(smem_u32(bufA + row * ROW_BYTES + c * 16),
                        reinterpret_cast<const uint4*>(g_zn + (I * 128 + row) * DIM) + c);
        }
        if (J != I) {
            char* bufB = bufA + TILE_BYTES;
            #pragma unroll
            for (int i = 0; i < 4; i++) {
                const int idx = tid + i * 256, row = idx >> 3, c = idx & 7;
                CP_ASYNC_16(smem_u32(bufB + row * ROW_BYTES + c * 16),
                            reinterpret_cast<const uint4*>(g_zn + (J * 128 + row) * DIM) + c);
            }
        }
        CP_ASYNC_COMMIT();
    };

    const uint32_t aLane =
        (uint32_t)((wm * 32 + ((lane >> 3) & 1) * 8 + (lane & 7)) * ROW_BYTES)
        + (uint32_t)((lane >> 4) * 16);
    const uint32_t bLane =
        (uint32_t)(((wn * 64) + (lane >> 4) * 8 + (lane & 7)) * ROW_BYTES)
        + (uint32_t)(((lane >> 3) & 1) * 16);

    const u64 C6 = dup2c(1.0f / 720.0f), C5 = dup2c(1.0f / 120.0f),
              C4 = dup2c(1.0f / 24.0f),  C3 = dup2c(1.0f / 6.0f),
              C2 = dup2c(0.5f),          C1 = dup2c(1.0f);

    int t = blockIdx.x;
    int I, J, In = 0, Jn = 0;
    decode_tile(t, I, J);
    issue(0, I, J);
    if (t + GRID_K2 < NTILES) {
        decode_tile(t + GRID_K2, In, Jn);
        issue(1, In, Jn);
    }
    int bufidx = 0;

    for (; t < NTILES; t += GRID_K2) {
        if (t + GRID_K2 < NTILES) CP_ASYNC_WAIT_1(); else CP_ASYNC_WAIT_0();
        __syncthreads();   // tile t visible; everyone past means tile t-1 reads done

        // prefetch tile t+2 into slot (bufidx+2)%3 — the one tile t-1 used; safe now
        int I2 = 0, J2 = 0;
        if (t + 2 * GRID_K2 < NTILES) {
            decode_tile(t + 2 * GRID_K2, I2, J2);
            int s2 = bufidx + 2; if (s2 >= 3) s2 -= 3;
            issue(s2, I2, J2);
        }

        const char* base = dynsm + bufidx * SLOT_BYTES;
        const uint32_t aBase = smem_u32(base) + aLane;
        const uint32_t bBase = smem_u32(base + (J != I ? TILE_BYTES : 0)) + bLane;

        float acc[2][8][4];
        #pragma unroll
        for (int mb = 0; mb < 2; mb++)
            #pragma unroll
            for (int j = 0; j < 8; j++)
                #pragma unroll
                for (int v = 0; v < 4; v++) acc[mb][j][v] = 0.0f;

        #pragma unroll
        for (int ks = 0; ks < 4; ks++) {          // 4 k-steps of 32 fp8
            uint32_t a0[4], a1[4];
            LDSM_X4(a0, aBase + ks * 32);
            LDSM_X4(a1, aBase + 16 * ROW_BYTES + ks * 32);
            #pragma unroll
            for (int nb = 0; nb < 4; nb++) {
                uint32_t b[4];
                LDSM_X4(b, bBase + nb * 16 * ROW_BYTES + ks * 32);
                MMA_FP8(acc[0][2 * nb],     a0, b[0], b[1]);
                MMA_FP8(acc[0][2 * nb + 1], a0, b[2], b[3]);
                MMA_FP8(acc[1][2 * nb],     a1, b[0], b[1]);
                MMA_FP8(acc[1][2 * nb + 1], a1, b[2], b[3]);
            }
        }

        // ---- packed epilogue: exp(2x) -> row/col partials (deg-6 Taylor) ----
        u64 prow[4] = {0ull, 0ull, 0ull, 0ull};
        u64 pcol[8];
        #pragma unroll
        for (int j = 0; j < 8; j++) pcol[j] = 0ull;

        #pragma unroll
        for (int mb = 0; mb < 2; mb++)
            #pragma unroll
            for (int jj = 0; jj < 8; jj++)
                #pragma unroll
                for (int vp = 0; vp < 2; vp++) {
                    u64 x = pk2(acc[mb][jj][2 * vp], acc[mb][jj][2 * vp + 1]);
                    u64 p = fma2(C6, x, C5);
                    p = fma2(p, x, C4);
                    p = fma2(p, x, C3);
                    p = fma2(p, x, C2);
                    p = fma2(p, x, C1);
                    p = fma2(p, x, C1);                 // ~exp(x)
                    prow[mb * 2 + vp] = fma2(p, p, prow[mb * 2 + vp]);  // += exp(2x)
                    pcol[jj]          = fma2(p, p, pcol[jj]);
                }

        // ---- row sums: quad reduce, atomic to stripe I rows ----
        #pragma unroll
        for (int k = 0; k < 4; k++) {
            prow[k] = fma2(C1, __shfl_xor_sync(0xffffffffu, prow[k], 1), prow[k]);
            prow[k] = fma2(C1, __shfl_xor_sync(0xffffffffu, prow[k], 2), prow[k]);
        }
        if ((lane & 3) == 0) {
            const int g = lane >> 2;
            const int rbase = I * 128 + wm * 32;
            float lo, hi;
            upk2(lo, hi, prow[0]); atomicAdd(&g_rowsum[rbase + g],      lo + hi);
            upk2(lo, hi, prow[1]); atomicAdd(&g_rowsum[rbase + g + 8],  lo + hi);
            upk2(lo, hi, prow[2]); atomicAdd(&g_rowsum[rbase + 16 + g], lo + hi);
            upk2(lo, hi, prow[3]); atomicAdd(&g_rowsum[rbase + 24 + g], lo + hi);
        }

        // ---- col sums (off-diagonal): shuffle reduce, direct atomics to stripe J ----
        if (J != I) {
            #pragma unroll
            for (int j = 0; j < 8; j++) {
                pcol[j] = fma2(C1, __shfl_xor_sync(0xffffffffu, pcol[j], 4),  pcol[j]);
                pcol[j] = fma2(C1, __shfl_xor_sync(0xffffffffu, pcol[j], 8),  pcol[j]);
                pcol[j] = fma2(C1, __shfl_xor_sync(0xffffffffu, pcol[j], 16), pcol[j]);
            }
            if (lane < 4) {
                #pragma unroll
                for (int j = 0; j < 8; j++) {
                    float lo, hi;
                    upk2(lo, hi, pcol[j]);
                    const int c = J * 128 + wn * 64 + (j >> 1) * 16 + (j & 1) * 8 + lane * 2;
                    atomicAdd(&g_rowsum[c],     lo);
                    atomicAdd(&g_rowsum[c + 1], hi);
                }
            }
        }

        I = In; J = Jn; In = I2; Jn = J2;
        bufidx++; if (bufidx == 3) bufidx = 0;
    }
}

// ===================== K3a: parallel log + reduce (atomic) =====================

__global__ void __launch_bounds__(256) k3a_reduce() {
    const int tid = threadIdx.x;
    const int g = blockIdx.x * 256 + tid;          // 16 blocks x 256 = 4096
    float s = logf(g_rowsum[g] - EXP_DIAG)
            + logf(g_rowsum[g + 4096] - EXP_DIAG)
            - 2.0f * g_pos[g];
    #pragma unroll
    for (int o = 16; o; o >>= 1) s += __shfl_xor_sync(0xffffffffu, s, o);
    __shared__ float red[8];
    if ((tid & 31) == 0) red[tid >> 5] = s;
    __syncthreads();
    if (tid == 0) {
        float tot = 0.0f;
        #pragma unroll
        for (int w = 0; w < 8; w++) tot += red[w];
        atomicAdd(&g_loss, tot);
    }
}

// ===================== K3b: finalize =====================

__global__ void k3b_final(float* __restrict__ out) {
    out[0] = g_loss / (float)NTOT;
}

// ===================== launch =====================

extern "C" void kernel_launch(void* const* d_in, const int* in_sizes, int n_in,
                              void* d_out, int out_size) {
    const float* zi = (const float*)d_in[0];
    const float* zj = (const float*)d_in[1];
    float* out = (float*)d_out;

    cudaFuncSetAttribute(k2_simsum, cudaFuncAttributeMaxDynamicSharedMemorySize, SMEM_BYTES);

    k1_normalize<<<BATCH / 8, 256>>>(zi, zj);
    k2_simsum<<<GRID_K2, 256, SMEM_BYTES>>>();
    k3a_reduce<<<16, 256>>>();
    k3b_final<<<1, 1>>>(out);
}

// round 10
// speedup vs baseline: 1.0462x; 1.0462x over previous
#include <cuda_runtime.h>
#include <cuda_bf16.h>
#include <cstdint>

// ===================== Problem constants =====================

#define BATCH 4096
#define NTOT  8192
#define DIM   128
#define NTILES 2080                       // 64*65/2 upper triangle incl diagonal
#define GRID_K2 296                       // 2 CTAs per SM

#define ROW_BYTES 144                     // 128 fp8 = 128B + 16B pad (conflict-free ldmatrix)
#define TILE_BYTES (128 * ROW_BYTES)      // 18432
#define SLOT_BYTES (2 * TILE_BYTES)       // A stripe + B stripe = 36864
#define SMEM_BYTES (2 * SLOT_BYTES)       // 73728/CTA, double-buffered (2 CTAs/SM ok)

#define EXP_DIAG 7.3890560989306495f      // e^2 self-similarity exp

// ===================== asm helpers (sm_100-safe, fp8 is sm_89+ standard) =====================

__device__ __forceinline__ uint32_t smem_u32(const void* smem_ptr) {
    uint32_t addr;
    asm("{ .reg .u64 tmp; cvta.to.shared.u64 tmp, %1; cvt.u32.u64 %0, tmp; }"
        : "=r"(addr) : "l"(smem_ptr));
    return addr;
}

#define LDSM_X4(r, addr) \
    asm volatile("ldmatrix.sync.aligned.m8n8.x4.shared.b16 {%0,%1,%2,%3}, [%4];" \
        : "=r"((r)[0]), "=r"((r)[1]), "=r"((r)[2]), "=r"((r)[3]) : "r"(addr))

// fp8 e4m3 MMA, m16n8k32: same fragment addressing as bf16 m16n8k16 (b16 -> 2 fp8)
#define MMA_FP8(d, a, b0, b1) \
    asm volatile("mma.sync.aligned.m16n8k32.row.col.f32.e4m3.e4m3.f32 " \
        "{%0,%1,%2,%3}, {%4,%5,%6,%7}, {%8,%9}, {%0,%1,%2,%3};" \
        : "+f"((d)[0]), "+f"((d)[1]), "+f"((d)[2]), "+f"((d)[3]) \
        : "r"((a)[0]), "r"((a)[1]), "r"((a)[2]), "r"((a)[3]), "r"(b0), "r"(b1))

#define CP_ASYNC_16(dst_smem, src_gmem) \
    asm volatile("cp.async.cg.shared.global [%0], [%1], 16;" \
        :: "r"(dst_smem), "l"(src_gmem) : "memory")

#define CP_ASYNC_COMMIT() asm volatile("cp.async.commit_group;" ::: "memory")
#define CP_ASYNC_WAIT_1() asm volatile("cp.async.wait_group 1;" ::: "memory")
#define CP_ASYNC_WAIT_0() asm volatile("cp.async.wait_group 0;" ::: "memory")

// ---- packed f32x2 ----

typedef unsigned long long u64;

__device__ __forceinline__ u64 pk2(float lo, float hi) {
    u64 r;
    asm("mov.b64 %0, {%1, %2};" : "=l"(r) : "f"(lo), "f"(hi));
    return r;
}
__device__ __forceinline__ void upk2(float& lo, float& hi, u64 v) {
    asm("mov.b64 {%0, %1}, %2;" : "=f"(lo), "=f"(hi) : "l"(v));
}
__device__ __forceinline__ u64 fma2(u64 a, u64 b, u64 c) {
    u64 d;
    asm("fma.rn.f32x2 %0, %1, %2, %3;" : "=l"(d) : "l"(a), "l"(b), "l"(c));
    return d;
}
__device__ __forceinline__ constexpr u64 dup2c(float f) {
    union { float f32; unsigned int u32; } u = { f };
    return ((u64)u.u32 << 32) | u.u32;
}

// float4 -> 4 packed e4m3 (v.x in byte 0)
__device__ __forceinline__ uint32_t f4_to_e4m3(float4 v) {
    uint16_t h01, h23;
    asm("cvt.rn.satfinite.e4m3x2.f32 %0, %1, %2;" : "=h"(h01) : "f"(v.y), "f"(v.x));
    asm("cvt.rn.satfinite.e4m3x2.f32 %0, %1, %2;" : "=h"(h23) : "f"(v.w), "f"(v.z));
    return (uint32_t)h01 | ((uint32_t)h23 << 16);
}

// ===================== Device scratch =====================

__device__ uint8_t g_zn[NTOT * DIM];     // normalized rows, e4m3
__device__ float g_pos[BATCH];           // pos_r = sim(r, r+B)/T, fp32 exact
__device__ float g_rowsum[NTOT];         // sum of exp per row (atomics)
__device__ unsigned g_done;              // finished-CTA counter (K2 tail)

// ===================== K1: normalize + positives =====================

__global__ void __launch_bounds__(256) k1_normalize(const float* __restrict__ zi,
                                                    const float* __restrict__ zj) {
    const int tid = threadIdx.x;
    const int lane = tid & 31;
    const int r = blockIdx.x * 8 + (tid >> 5);   // 512 blocks x 8 warps

    const float4 va = reinterpret_cast<const float4*>(zi + r * DIM)[lane];
    const float4 vb = reinterpret_cast<const float4*>(zj + r * DIM)[lane];
    float sa  = va.x*va.x + va.y*va.y + va.z*va.z + va.w*va.w;
    float sb  = vb.x*vb.x + vb.y*vb.y + vb.z*vb.z + vb.w*vb.w;
    float sab = va.x*vb.x + va.y*vb.y + va.z*vb.z + va.w*vb.w;
    #pragma unroll
    for (int o = 16; o; o >>= 1) {
        sa  += __shfl_xor_sync(0xffffffffu, sa,  o);
        sb  += __shfl_xor_sync(0xffffffffu, sb,  o);
        sab += __shfl_xor_sync(0xffffffffu, sab, o);
    }
    const float ri = rsqrtf(fmaxf(sa, 1e-16f));
    const float rj = rsqrtf(fmaxf(sb, 1e-16f));

    float4 na = make_float4(va.x * ri, va.y * ri, va.z * ri, va.w * ri);
    float4 nb = make_float4(vb.x * rj, vb.y * rj, vb.z * rj, vb.w * rj);
    reinterpret_cast<uint32_t*>(g_zn + r * DIM)[lane]           = f4_to_e4m3(na);
    reinterpret_cast<uint32_t*>(g_zn + (r + BATCH) * DIM)[lane] = f4_to_e4m3(nb);

    if (lane == 0) g_pos[r] = sab * ri * rj * 2.0f;   // /T = *2
    if (blockIdx.x < 32) g_rowsum[blockIdx.x * 256 + tid] = 0.0f;
    if (blockIdx.x == 0 && tid == 0) g_done = 0u;
}

// ===================== K2: symmetric fp8 GEMM + exp + row/col sums + fused finalize ==========
//
// 296 persistent CTAs (2/SM) over 2080 upper-triangle 128x128 tiles. 256 threads,
// warp grid 4x2. Double-buffered (R8 config, proven 46us). After the loop the
// LAST CTA (done-counter protocol) computes the log-sum finalize — no K3 launch.

__device__ __forceinline__ void decode_tile(int t, int& I, int& J) {
    int i = (int)(64.5f - sqrtf(64.5f * 64.5f - 2.0f * (float)t));
    while (i * (129 - i) / 2 > t) i--;
    while ((i + 1) * (128 - i) / 2 <= t) i++;
    I = i;
    J = i + (t - i * (129 - i) / 2);
}

__global__ void __launch_bounds__(256, 2) k2_simsum(float* __restrict__ out) {
    extern __shared__ __align__(16) char dynsm[];

    const int tid = threadIdx.x;
    const int wid = tid >> 5;
    const int lane = tid & 31;
    const int wm = wid & 3;        // 4 row bands of 32
    const int wn = wid >> 2;       // 2 col halves of 64

    auto issue = [&](int slot, int I, int J) {
        char* bufA = dynsm + slot * SLOT_BYTES;
        #pragma unroll
        for (int i = 0; i < 4; i++) {
            const int idx = tid + i * 256, row = idx >> 3, c = idx & 7;
            CP_ASYNC_16(smem_u32(bufA + row * ROW_BYTES + c * 16),
                        reinterpret_cast<const uint4*>(g_zn + (I * 128 + row) * DIM) + c);
        }
        if (J != I) {
            char* bufB = bufA + TILE_BYTES;
            #pragma unroll
            for (int i = 0; i < 4; i++) {
                const int idx = tid + i * 256, row = idx >> 3, c = idx & 7;
                CP_ASYNC_16(smem_u32(bufB + row * ROW_BYTES + c * 16),
                            reinterpret_cast<const uint4*>(g_zn + (J * 128 + row) * DIM) + c);
            }
        }
        CP_ASYNC_COMMIT();
    };

    const uint32_t aLane =
        (uint32_t)((wm * 32 + ((lane >> 3) & 1) * 8 + (lane & 7)) * ROW_BYTES)
        + (uint32_t)((lane >> 4) * 16);
    const uint32_t bLane =
        (uint32_t)(((wn * 64) + (lane >> 4) * 8 + (lane & 7)) * ROW_BYTES)
        + (uint32_t)(((lane >> 3) & 1) * 16);

    const u64 C6 = dup2c(1.0f / 720.0f), C5 = dup2c(1.0f / 120.0f),
              C4 = dup2c(1.0f / 24.0f),  C3 = dup2c(1.0f / 6.0f),
              C2 = dup2c(0.5f),          C1 = dup2c(1.0f);

    int t = blockIdx.x;
    int I, J, In = 0, Jn = 0;
    decode_tile(t, I, J);
    issue(0, I, J);
    int slot = 0;

    for (; t < NTILES; t += GRID_K2) {
        const int tn = t + GRID_K2;
        if (tn < NTILES) {
            decode_tile(tn, In, Jn);
            issue(slot ^ 1, In, Jn);
            CP_ASYNC_WAIT_1();
        } else {
            CP_ASYNC_WAIT_0();
        }
        __syncthreads();   // tile t visible; everyone done reading slot from t-1

        const char* base = dynsm + slot * SLOT_BYTES;
        const uint32_t aBase = smem_u32(base) + aLane;
        const uint32_t bBase = smem_u32(base + (J != I ? TILE_BYTES : 0)) + bLane;

        float acc[2][8][4];
        #pragma unroll
        for (int mb = 0; mb < 2; mb++)
            #pragma unroll
            for (int j = 0; j < 8; j++)
                #pragma unroll
                for (int v = 0; v < 4; v++) acc[mb][j][v] = 0.0f;

        #pragma unroll
        for (int ks = 0; ks < 4; ks++) {          // 4 k-steps of 32 fp8
            uint32_t a0[4], a1[4];
            LDSM_X4(a0, aBase + ks * 32);
            LDSM_X4(a1, aBase + 16 * ROW_BYTES + ks * 32);
            #pragma unroll
            for (int nb = 0; nb < 4; nb++) {
                uint32_t b[4];
                LDSM_X4(b, bBase + nb * 16 * ROW_BYTES + ks * 32);
                MMA_FP8(acc[0][2 * nb],     a0, b[0], b[1]);
                MMA_FP8(acc[0][2 * nb + 1], a0, b[2], b[3]);
                MMA_FP8(acc[1][2 * nb],     a1, b[0], b[1]);
                MMA_FP8(acc[1][2 * nb + 1], a1, b[2], b[3]);
            }
        }

        // ---- packed epilogue: exp(2x) -> row/col partials (deg-6 Taylor) ----
        u64 prow[4] = {0ull, 0ull, 0ull, 0ull};
        u64 pcol[8];
        #pragma unroll
        for (int j = 0; j < 8; j++) pcol[j] = 0ull;

        #pragma unroll
        for (int mb = 0; mb < 2; mb++)
            #pragma unroll
            for (int jj = 0; jj < 8; jj++)
                #pragma unroll
                for (int vp = 0; vp < 2; vp++) {
                    u64 x = pk2(acc[mb][jj][2 * vp], acc[mb][jj][2 * vp + 1]);
                    u64 p = fma2(C6, x, C5);
                    p = fma2(p, x, C4);
                    p = fma2(p, x, C3);
                    p = fma2(p, x, C2);
                    p = fma2(p, x, C1);
                    p = fma2(p, x, C1);                 // ~exp(x)
                    prow[mb * 2 + vp] = fma2(p, p, prow[mb * 2 + vp]);  // += exp(2x)
                    pcol[jj]          = fma2(p, p, pcol[jj]);
                }

        // ---- row sums: quad reduce, atomic to stripe I rows ----
        #pragma unroll
        for (int k = 0; k < 4; k++) {
            prow[k] = fma2(C1, __shfl_xor_sync(0xffffffffu, prow[k], 1), prow[k]);
            prow[k] = fma2(C1, __shfl_xor_sync(0xffffffffu, prow[k], 2), prow[k]);
        }
        if ((lane & 3) == 0) {
            const int g = lane >> 2;
            const int rbase = I * 128 + wm * 32;
            float lo, hi;
            upk2(lo, hi, prow[0]); atomicAdd(&g_rowsum[rbase + g],      lo + hi);
            upk2(lo, hi, prow[1]); atomicAdd(&g_rowsum[rbase + g + 8],  lo + hi);
            upk2(lo, hi, prow[2]); atomicAdd(&g_rowsum[rbase + 16 + g], lo + hi);
            upk2(lo, hi, prow[3]); atomicAdd(&g_rowsum[rbase + 24 + g], lo + hi);
        }

        // ---- col sums (off-diagonal): shuffle reduce, direct atomics to stripe J ----
        if (J != I) {
            #pragma unroll
            for (int j = 0; j < 8; j++) {
                pcol[j] = fma2(C1, __shfl_xor_sync(0xffffffffu, pcol[j], 4),  pcol[j]);
                pcol[j] = fma2(C1, __shfl_xor_sync(0xffffffffu, pcol[j], 8),  pcol[j]);
                pcol[j] = fma2(C1, __shfl_xor_sync(0xffffffffu, pcol[j], 16), pcol[j]);
            }
            if (lane < 4) {
                #pragma unroll
                for (int j = 0; j < 8; j++) {
                    float lo, hi;
                    upk2(lo, hi, pcol[j]);
                    const int c = J * 128 + wn * 64 + (j >> 1) * 16 + (j & 1) * 8 + lane * 2;
                    atomicAdd(&g_rowsum[c],     lo);
                    atomicAdd(&g_rowsum[c + 1], hi);
                }
            }
        }

        __syncthreads();   // all reads of this slot done before it is re-issued
        I = In; J = Jn; slot ^= 1;
    }

    // ======== fused finalize: last CTA computes the loss ========
    __threadfence();                       // my atomics globally visible
    __shared__ unsigned s_last;
    if (tid == 0) s_last = (atomicAdd(&g_done, 1u) == GRID_K2 - 1u) ? 1u : 0u;
    __syncthreads();
    if (s_last) {
        // all other CTAs incremented AFTER their fence -> all rowsums visible
        float s = 0.0f;
        #pragma unroll
        for (int i = 0; i < NTOT / 256; i++)
            s += logf(g_rowsum[tid + i * 256] - EXP_DIAG);
        #pragma unroll
        for (int i = 0; i < BATCH / 256; i++)
            s -= 2.0f * g_pos[tid + i * 256];
        #pragma unroll
        for (int o = 16; o; o >>= 1) s += __shfl_xor_sync(0xffffffffu, s, o);
        __shared__ float red[8];
        if (lane == 0) red[wid] = s;
        __syncthreads();
        if (tid == 0) {
            float tot = 0.0f;
            #pragma unroll
            for (int w = 0; w < 8; w++) tot += red[w];
            out[0] = tot / (float)NTOT;
        }
    }
}

// ===================== launch =====================

extern "C" void kernel_launch(void* const* d_in, const int* in_sizes, int n_in,
                              void* d_out, int out_size) {
    const float* zi = (const float*)d_in[0];
    const float* zj = (const float*)d_in[1];
    float* out = (float*)d_out;

    cudaFuncSetAttribute(k2_simsum, cudaFuncAttributeMaxDynamicSharedMemorySize, SMEM_BYTES);

    k1_normalize<<<BATCH / 8, 256>>>(zi, zj);
    k2_simsum<<<GRID_K2, 256, SMEM_BYTES>>>(out);
}